// round 5
// baseline (speedup 1.0000x reference)
#include <cuda_runtime.h>

#define FULLMASK 0xffffffffu

constexpr int   B_     = 256;
constexpr int   T_     = 256;
constexpr int   C_     = 1024;
constexpr int   L_     = 32;
constexpr int   S_     = 65;      // 2*L+1 extended states
constexpr int   SP_    = 34;      // compact row: [blank, lab0..lab31, pad0]
constexpr int   BLANK_ = C_ - 1;
constexpr float PRE    = 512.0f;  // 2^9 per-step prescale
constexpr int   PRE_E  = 9;
constexpr float EPS    = 1e-7f;
constexpr float EPS_S  = EPS * PRE;

// cross-CTA exchange (zero-init at load; flag self-resets each run)
__device__ float g_ex[2][B_][66];
__device__ int   g_exE[2][B_];
__device__ int   g_flag[B_];

__device__ __forceinline__ int kidx(int s) {
    return (s >= S_) ? 33 : ((s & 1) ? ((s >> 1) + 1) : 0);
}
__device__ __forceinline__ float allow_fwd(int s, const int* labs) {
    if (!(s & 1) || s >= S_) return 0.0f;
    const int j = (s - 1) >> 1;
    return (j == 0 || labs[j] != labs[j - 1]) ? 1.0f : 0.0f;
}
__device__ __forceinline__ float allow_bwd(int s, const int* labs) {
    if (!(s & 1) || (s + 2) > S_ - 1) return 0.0f;
    const int jn = (s + 1) >> 1, jp = (s - 1) >> 1;
    return (labs[jn] != labs[jp]) ? 1.0f : 0.0f;
}
__device__ __forceinline__ int renorm(float& r0, float& r1, float& r2) {
    float m = fmaxf(fmaxf(r0, r1), r2);
#pragma unroll
    for (int o = 16; o; o >>= 1)
        m = fmaxf(m, __shfl_xor_sync(FULLMASK, m, o));
    const int e = (__float_as_int(m) >> 23) - 127;
    const float sc = __int_as_float((127 - e) << 23);  // exact 2^-e
    r0 *= sc; r1 *= sc; r2 *= sc;
    return e;
}
__device__ __forceinline__ float ldg_cg(const float* p) {
    float v;
    asm volatile("ld.global.cg.f32 %0, [%1];" : "=f"(v) : "l"(p));
    return v;
}
__device__ __forceinline__ float ldcg_f(const float* p) {
    float v;
    asm volatile("ld.global.cg.f32 %0, [%1];" : "=f"(v) : "l"(p));
    return v;
}

__global__ __launch_bounds__(128, 4)
void ctc_split_kernel(const int* __restrict__ y_true,
                      const float* __restrict__ y_pred,
                      float* __restrict__ out)
{
    __shared__ float slab[128 * SP_];   // 17408 B: this CTA's 128 time rows
    __shared__ int   labs[L_];
    __shared__ int   sh_old;

    const int bid  = blockIdx.x;
    const int b    = bid >> 1;
    const int dir  = bid & 1;            // 0 = forward half, 1 = backward half
    const int tid  = threadIdx.x;
    const int lane = tid & 31;
    const int wid  = tid >> 5;

    if (tid < L_) labs[tid] = __ldg(y_true + b * L_ + tid);
    __syncthreads();

    const float* base = y_pred + (size_t)b * T_ * C_;

    // gather one 32-row stage starting at local row lr0 (global t = 128*dir+lr)
    auto gather_stage = [&](int lr0, int t0, int nth) {
        for (int f = t0; f < 32 * 33; f += nth) {
            const int rl  = f / 33;
            const int c   = f - rl * 33;
            const int lr  = lr0 + rl;
            const int cls = c ? labs[c - 1] : BLANK_;
            const float v = ldg_cg(base + (size_t)(128 * dir + lr) * C_ + cls);
            slab[lr * SP_ + c] = fmaf(v, PRE, EPS_S);
        }
        for (int r = t0; r < 32; r += nth)
            slab[(lr0 + r) * SP_ + 33] = 0.0f;
    };

    // stage s local start row: fwd 32s ; bwd 96-32s (global t descending)
    auto stage_lr0 = [&](int s) { return dir ? (96 - 32 * s) : (32 * s); };

    // stage 0: all 4 warps
    gather_stage(stage_lr0(0), tid, 128);
    __syncthreads();

    // ---- scan state (warp 0 only) ----
    const int s0 = 3 * lane, s1 = s0 + 1, s2 = s0 + 2;
    const int k0 = kidx(s0), k1 = kidx(s1), k2 = kidx(s2);

    float a0, a1, a2;
    if (dir == 0) { a0 = allow_fwd(s0, labs); a1 = allow_fwd(s1, labs); a2 = allow_fwd(s2, labs); }
    else          { a0 = allow_bwd(s0, labs); a1 = allow_bwd(s1, labs); a2 = allow_bwd(s2, labs); }

    float r0 = 0.0f, r1 = 0.0f, r2 = 0.0f;
    int   E  = 0;
    int   ilb = 0, ill = 0;
    if (wid == 0 && dir == 1) {
        const int lab = labs[lane];
        const unsigned nzm = __ballot_sync(FULLMASK, lab != 0);
        const int len = __popc(nzm);
        ilb = 2 * len;
        ill = 2 * len - 1;
        if (ill < 0) ill += S_;
    }

    // ---- pipeline: iter k scans chunk k-1 while warps 1..3 gather stage k ---
    for (int k = 1; k <= 4; ++k) {
        const int q = k - 1;
        if (wid == 0) {
            if (dir == 0) {
                // forward chunk q over global t in [max(1,32q), 32q+32)
                if (q == 0 && lane == 0) { r0 = slab[0]; r1 = slab[1]; }
                const int tlo = (q == 0) ? 1 : 32 * q;
                const int thi = 32 * q + 32;
#pragma unroll 4
                for (int t = tlo; t < thi; ++t) {
                    const float* sr = slab + t * SP_;
                    const float p0 = sr[k0], p1 = sr[k1], p2 = sr[k2];
                    float u1 = __shfl_up_sync(FULLMASK, r1, 1);
                    float u2 = __shfl_up_sync(FULLMASK, r2, 1);
                    if (lane == 0) { u1 = 0.0f; u2 = 0.0f; }
                    const float n0 = p0 * fmaf(a0, u1, r0 + u2);
                    const float n1 = p1 * fmaf(a1, u2, r1 + r0);
                    const float n2 = p2 * fmaf(a2, r0, r2 + r1);
                    r0 = n0; r1 = n1; r2 = n2;
                    if ((t & 7) == 0) E += renorm(r0, r1, r2);
                }
            } else {
                // backward chunk q over global t from thi down to tlo
                if (q == 0) {
                    const float* sr = slab + 127 * SP_;   // global t = 255
                    r0 = (s0 == ilb || s0 == ill) ? sr[k0] : 0.0f;
                    r1 = (s1 == ilb || s1 == ill) ? sr[k1] : 0.0f;
                    r2 = (s2 == ilb || s2 == ill) ? sr[k2] : 0.0f;
                }
                const int thi = (q == 0) ? 254 : (255 - 32 * q);
                const int tlo = 224 - 32 * q;
#pragma unroll 4
                for (int t = thi; t >= tlo; --t) {
                    const float* sr = slab + (t - 128) * SP_;
                    const float p0 = sr[k0], p1 = sr[k1], p2 = sr[k2];
                    const float u0 = __shfl_down_sync(FULLMASK, r0, 1);
                    const float u1 = __shfl_down_sync(FULLMASK, r1, 1);
                    const float B0 = fmaf(a0, r2, r0 + r1);
                    const float B1 = fmaf(a1, u0, r1 + r2);
                    const float B2 = fmaf(a2, u1, r2 + u0);
                    r0 = p0 * B0; r1 = p1 * B1; r2 = p2 * B2;
                    if ((t & 7) == 0) E += renorm(r0, r1, r2);
                }
            }
        } else if (k <= 3) {
            gather_stage(stage_lr0(k), tid - 32, 96);
        }
        __syncthreads();
    }

    // ---- publish this direction's state at the t=127/128 boundary ----
    if (wid == 0) {
        if (dir == 1) {
            // finish: beta_127 combine (no p multiply) from c_128
            const float u0 = __shfl_down_sync(FULLMASK, r0, 1);
            const float u1 = __shfl_down_sync(FULLMASK, r1, 1);
            const float B0 = fmaf(a0, r2, r0 + r1);
            const float B1 = fmaf(a1, u0, r1 + r2);
            const float B2 = fmaf(a2, u1, r2 + u0);
            r0 = B0; r1 = B1; r2 = B2;
        }
        if (lane < 22) {
            g_ex[dir][b][s0] = r0;
            g_ex[dir][b][s1] = r1;
            g_ex[dir][b][s2] = r2;
        }
        if (lane == 0) g_exE[dir][b] = E;
    }
    __syncthreads();

    if (tid == 0) {
        __threadfence();
        sh_old = atomicAdd(&g_flag[b], 1);
    }
    __syncthreads();

    // second CTA of the pair combines: P = sum_s alpha_127[s] * beta_127[s]
    if (sh_old == 1 && wid == 0) {
        float part = 0.0f;
        if (lane < 22) {
            part  = ldcg_f(&g_ex[0][b][s0]) * ldcg_f(&g_ex[1][b][s0]);
            part += ldcg_f(&g_ex[0][b][s1]) * ldcg_f(&g_ex[1][b][s1]);
            part += ldcg_f(&g_ex[0][b][s2]) * ldcg_f(&g_ex[1][b][s2]);
        }
#pragma unroll
        for (int o = 16; o; o >>= 1)
            part += __shfl_xor_sync(FULLMASK, part, o);
        if (lane == 0) {
            const float LN2 = 0.6931471805599453f;
            int eTot;
            asm volatile("ld.global.cg.s32 %0, [%1];" : "=r"(eTot)
                         : "l"(&g_exE[0][b]));
            int eB;
            asm volatile("ld.global.cg.s32 %0, [%1];" : "=r"(eB)
                         : "l"(&g_exE[1][b]));
            eTot += eB;
            out[b] = -(logf(part) + (float)(eTot - PRE_E * T_) * LN2);
            g_flag[b] = 0;   // reset for next graph replay
        }
    }
}

extern "C" void kernel_launch(void* const* d_in, const int* in_sizes, int n_in,
                              void* d_out, int out_size)
{
    (void)n_in; (void)out_size;
    const int*   y_true;
    const float* y_pred;
    if (in_sizes[0] == B_ * L_) {
        y_true = (const int*)d_in[0];
        y_pred = (const float*)d_in[1];
    } else {
        y_true = (const int*)d_in[1];
        y_pred = (const float*)d_in[0];
    }
    ctc_split_kernel<<<2 * B_, 128>>>(y_true, y_pred, (float*)d_out);
}